// round 10
// baseline (speedup 1.0000x reference)
#include <cuda_runtime.h>
#include <cuda_bf16.h>
#include <math.h>
#include <stdint.h>

#define N_PATCH 676
#define NPAD    768
#define NPT     6          // patch tiles of 128
#define D       384
#define M       200000
#define NTILES  1563       // lib tiles of 128
#define NKB     6          // k-blocks of 64
#define IMG     224
#define KS      33
#define RAD     16
#define T5B     250        // dstar_top5 blocks

typedef unsigned long long ull;

__device__ __align__(16) __nv_bfloat16 g_patchh[NPAD * D];
__device__ float g_patchN[NPAD * D];
__device__ float g_pn[NPAD];
__device__ float g_ln[M];
__device__ ull   g_mink[NPAD];      // global per-patch-col min key (atomicMin)
__device__ float g_minval[N_PATCH];
__device__ int   g_sidx;
__device__ int   g_mstar;
__device__ float g_sstar;
__device__ ull   g_part[T5B * 5];

__device__ __forceinline__ uint32_t smem_u32(const void* p) {
    uint32_t a;
    asm("{ .reg .u64 t; cvta.to.shared.u64 t, %1; cvt.u32.u64 %0, t; }" : "=r"(a) : "l"(p));
    return a;
}
#define SW128(x) ((x) ^ (((x) >> 3) & 0x70))

#define CP16(dst, src) asm volatile("cp.async.cg.shared.global [%0], [%1], 16;" :: "r"(dst), "l"(src) : "memory")
#define CP_COMMIT()    asm volatile("cp.async.commit_group;" ::: "memory")
#define CP_WAIT1()     asm volatile("cp.async.wait_group 1;" ::: "memory")
#define CP_WAIT0()     asm volatile("cp.async.wait_group 0;" ::: "memory")

#define STS128(addr, v) \
    asm volatile("st.shared.v4.b32 [%0], {%1,%2,%3,%4};" \
        :: "r"(addr), "r"((v).x), "r"((v).y), "r"((v).z), "r"((v).w) : "memory")

#define LDSM4(r0, r1, r2, r3, addr) \
    asm volatile("ldmatrix.sync.aligned.m8n8.x4.shared.b16 {%0,%1,%2,%3}, [%4];" \
        : "=r"(r0), "=r"(r1), "=r"(r2), "=r"(r3) : "r"(addr))

#define MMA16816(c, a, b0, b1) \
    asm volatile("mma.sync.aligned.m16n8k16.row.col.f32.bf16.bf16.f32 " \
        "{%0,%1,%2,%3}, {%4,%5,%6,%7}, {%8,%9}, {%0,%1,%2,%3};" \
        : "+f"((c)[0]), "+f"((c)[1]), "+f"((c)[2]), "+f"((c)[3]) \
        : "r"((a)[0]), "r"((a)[1]), "r"((a)[2]), "r"((a)[3]), "r"(b0), "r"(b1))

__device__ __forceinline__ unsigned f2ord(float v) {
    unsigned u = __float_as_uint(v);
    return (u & 0x80000000u) ? ~u : (u | 0x80000000u);
}
__device__ __forceinline__ float ord2f(unsigned o) {
    unsigned u = (o & 0x80000000u) ? (o & 0x7fffffffu) : ~o;
    return __uint_as_float(u);
}

__device__ __forceinline__ float dot4f(float4 a, float4 b) {
    return a.x * b.x + a.y * b.y + a.z * b.z + a.w * b.w;
}

// ---------------- 1) normalize patch -> fp32 + bf16, pn; init g_mink ----------------
__global__ void prep_kernel(const float* __restrict__ patch) {
    int n = blockIdx.x, t = threadIdx.x;   // 128 threads
    __shared__ float red[4];
    __shared__ float bcast;
    if (t == 0) g_mink[n] = ~0ull;
    if (n >= N_PATCH) {
        for (int c = t; c < D; c += 128) {
            g_patchN[(size_t)n * D + c] = 0.f;
            g_patchh[(size_t)n * D + c] = __float2bfloat16(0.f);
        }
        if (t == 0) g_pn[n] = 0.f;
        return;
    }
    float x0 = patch[(size_t)n * D + t];
    float x1 = patch[(size_t)n * D + t + 128];
    float x2 = patch[(size_t)n * D + t + 256];
    float s = x0 * x0 + x1 * x1 + x2 * x2;
    for (int o = 16; o > 0; o >>= 1) s += __shfl_down_sync(0xffffffffu, s, o);
    if ((t & 31) == 0) red[t >> 5] = s;
    __syncthreads();
    if (t == 0) bcast = red[0] + red[1] + red[2] + red[3];
    __syncthreads();
    float inv = 1.f / fmaxf(sqrtf(bcast), 1e-12f);
    float y0 = x0 * inv, y1 = x1 * inv, y2 = x2 * inv;
    g_patchN[(size_t)n * D + t]       = y0;
    g_patchN[(size_t)n * D + t + 128] = y1;
    g_patchN[(size_t)n * D + t + 256] = y2;
    g_patchh[(size_t)n * D + t]       = __float2bfloat16(y0);
    g_patchh[(size_t)n * D + t + 128] = __float2bfloat16(y1);
    g_patchh[(size_t)n * D + t + 256] = __float2bfloat16(y2);
    float p = y0 * y0 + y1 * y1 + y2 * y2;
    for (int o = 16; o > 0; o >>= 1) p += __shfl_down_sync(0xffffffffu, p, o);
    if ((t & 31) == 0) red[t >> 5] = p;
    __syncthreads();
    if (t == 0) g_pn[n] = red[0] + red[1] + red[2] + red[3];
}

// ---------------- 2) bf16 HMMA GEMM, fp32 A converted in-flight, ln fused ----------------
// A stages (bf16) @ 0/16384, B stages (bf16) @ 32768/49152. 64KB dyn smem.
#define SMEM_DYN 65536

__global__ void __launch_bounds__(256, 2) gemm_bf16(const float* __restrict__ lib) {
    extern __shared__ char dyn[];
    __shared__ float ln_s[128];
    __shared__ ull scmb[2][128];

    int t = threadIdx.x;
    int pt = blockIdx.x;       // patch tile (fast -> lib tile L2 reuse)
    int tile = blockIdx.y;     // lib tile
    int lane = t & 31, warp = t >> 5;
    int wm = warp >> 2, wn = warp & 3;

    uint32_t sbase = smem_u32(dyn);
    const float* gA = lib + (size_t)tile * 128 * D;           // fp32 lib tile
    const char* gB = (const char*)g_patchh + (size_t)pt * 128 * 768;

    int arow = t >> 3;         // local row base (0..31), rows arow+32i
    int aseg = t & 7;          // 8-float segment within the 64-col k-block
    float acc0 = 0.f, acc1 = 0.f, acc2 = 0.f, acc3 = 0.f;

    // A loader: fp32 LDG -> bf16 cvt -> STS (row mapping identical to cp.async version)
#define LOADA(kb_, sb_) do { \
        _Pragma("unroll") \
        for (int i_ = 0; i_ < 4; i_++) { \
            int row_ = arow + 32 * i_; \
            float4 v0 = make_float4(0.f, 0.f, 0.f, 0.f); \
            float4 v1 = v0; \
            if (tile * 128 + row_ < M) { \
                const float4* p_ = (const float4*)(gA + (size_t)row_ * D + (kb_) * 64) + aseg * 2; \
                v0 = p_[0]; v1 = p_[1]; \
            } \
            float ss_ = v0.x * v0.x + v0.y * v0.y + v0.z * v0.z + v0.w * v0.w \
                      + v1.x * v1.x + v1.y * v1.y + v1.z * v1.z + v1.w * v1.w; \
            if (i_ == 0) acc0 += ss_; else if (i_ == 1) acc1 += ss_; \
            else if (i_ == 2) acc2 += ss_; else acc3 += ss_; \
            __nv_bfloat162 p0_ = __float22bfloat162_rn(make_float2(v0.x, v0.y)); \
            __nv_bfloat162 p1_ = __float22bfloat162_rn(make_float2(v0.z, v0.w)); \
            __nv_bfloat162 p2_ = __float22bfloat162_rn(make_float2(v1.x, v1.y)); \
            __nv_bfloat162 p3_ = __float22bfloat162_rn(make_float2(v1.z, v1.w)); \
            uint4 o_; \
            o_.x = *reinterpret_cast<unsigned*>(&p0_); \
            o_.y = *reinterpret_cast<unsigned*>(&p1_); \
            o_.z = *reinterpret_cast<unsigned*>(&p2_); \
            o_.w = *reinterpret_cast<unsigned*>(&p3_); \
            STS128((sb_) + SW128((uint32_t)(row_ * 128 + aseg * 16)), o_); \
        } \
    } while (0)

#define LOADB(kb_, sb_) do { \
        _Pragma("unroll") \
        for (int i_ = 0; i_ < 4; i_++) { \
            int id_ = i_ * 256 + t; int row_ = id_ >> 3, seg_ = id_ & 7; \
            uint32_t off_ = SW128((uint32_t)(row_ * 128 + seg_ * 16)); \
            CP16((sb_) + off_, gB + (size_t)(kb_) * 128 + (size_t)row_ * 768 + seg_ * 16); \
        } \
        CP_COMMIT(); \
    } while (0)

    // preload k-block 0
    LOADA(0, sbase);
    LOADB(0, sbase + 32768);

    float c[4][4][4];
#pragma unroll
    for (int mi = 0; mi < 4; mi++)
#pragma unroll
        for (int ni = 0; ni < 4; ni++)
#pragma unroll
            for (int k = 0; k < 4; k++) c[mi][ni][k] = 0.f;

    for (int kb = 0; kb < NKB; kb++) {
        int buf = kb & 1;
        if (kb < NKB - 1) {
            int nb = buf ^ 1;
            LOADA(kb + 1, sbase + nb * 16384);
            LOADB(kb + 1, sbase + 32768 + nb * 16384);
            CP_WAIT1();
        } else {
            CP_WAIT0();
        }
        __syncthreads();
        uint32_t sA = sbase + buf * 16384;
        uint32_t sB = sbase + 32768 + buf * 16384;
#pragma unroll
        for (int ks = 0; ks < 4; ks++) {
            uint32_t a[4][4];
#pragma unroll
            for (int mi = 0; mi < 4; mi++) {
                uint32_t byte = (uint32_t)((wm * 64 + mi * 16 + (lane & 15)) * 128
                                           + ks * 32 + (lane >> 4) * 16);
                LDSM4(a[mi][0], a[mi][1], a[mi][2], a[mi][3], sA + SW128(byte));
            }
            uint32_t b[4][2];
#pragma unroll
            for (int nh = 0; nh < 2; nh++) {
                uint32_t byte = (uint32_t)((wn * 32 + nh * 16 + (lane & 15)) * 128
                                           + ks * 32 + (lane >> 4) * 16);
                uint32_t r0, r1, r2, r3;
                LDSM4(r0, r1, r2, r3, sB + SW128(byte));
                b[nh * 2][0] = r0; b[nh * 2 + 1][0] = r1;
                b[nh * 2][1] = r2; b[nh * 2 + 1][1] = r3;
            }
#pragma unroll
            for (int mi = 0; mi < 4; mi++)
#pragma unroll
                for (int ni = 0; ni < 4; ni++)
                    MMA16816(c[mi][ni], a[mi], b[ni][0], b[ni][1]);
        }
        __syncthreads();
    }

    // ln: reduce per-row sumsq over the 8 seg-threads (lanes grouped by 8)
    {
        float av[4] = {acc0, acc1, acc2, acc3};
#pragma unroll
        for (int i = 0; i < 4; i++) {
            float s = av[i];
            s += __shfl_xor_sync(0xffffffffu, s, 1);
            s += __shfl_xor_sync(0xffffffffu, s, 2);
            s += __shfl_xor_sync(0xffffffffu, s, 4);
            int row = arow + 32 * i;
            int grow = tile * 128 + row;
            float lnv = (grow < M) ? s : 1e30f;
            if (aseg == 0) {
                ln_s[row] = lnv;
                if (pt == 0 && grow < M) g_ln[grow] = lnv;
            }
        }
    }
    __syncthreads();

    // epilogue: key = (f2ord(ln - 2 dot) << 32) | lib_row ; min over 128 rows per col
    unsigned rbase = (unsigned)tile * 128u + (unsigned)(wm * 64) + (unsigned)(lane >> 2);
#pragma unroll
    for (int ni = 0; ni < 4; ni++) {
        ull k0 = ~0ull, k1 = ~0ull;
#pragma unroll
        for (int mi = 0; mi < 4; mi++) {
            int rloc = wm * 64 + mi * 16 + (lane >> 2);
            float l0 = ln_s[rloc], l1 = ln_s[rloc + 8];
            unsigned r0 = rbase + mi * 16, r1 = r0 + 8;
            float v; ull k;
            v = fmaf(-2.f, c[mi][ni][0], l0); k = ((ull)f2ord(v) << 32) | r0; k0 = min(k0, k);
            v = fmaf(-2.f, c[mi][ni][2], l1); k = ((ull)f2ord(v) << 32) | r1; k0 = min(k0, k);
            v = fmaf(-2.f, c[mi][ni][1], l0); k = ((ull)f2ord(v) << 32) | r0; k1 = min(k1, k);
            v = fmaf(-2.f, c[mi][ni][3], l1); k = ((ull)f2ord(v) << 32) | r1; k1 = min(k1, k);
        }
#pragma unroll
        for (int off = 4; off < 32; off <<= 1) {
            k0 = min(k0, __shfl_xor_sync(0xffffffffu, k0, off));
            k1 = min(k1, __shfl_xor_sync(0xffffffffu, k1, off));
        }
        if (lane < 4) {
            scmb[wm][wn * 32 + ni * 8 + lane * 2 + 0] = k0;
            scmb[wm][wn * 32 + ni * 8 + lane * 2 + 1] = k1;
        }
    }
    __syncthreads();
    if (t < 128)
        atomicMin(&g_mink[pt * 128 + t], min(scmb[0][t], scmb[1][t]));
}

// ---------------- 3) finalize minval + argmax over patch rows ----------------
__global__ void argmax_kernel() {
    int t = threadIdx.x;  // 768
    __shared__ float sv[768];
    __shared__ int si[768];
    __shared__ ull skey[768];
    float val = -3.4e38f;
    ull key = ~0ull;
    if (t < N_PATCH) {
        key = g_mink[t];
        float v = ord2f((unsigned)(key >> 32));
        val = sqrtf(fmaxf(g_pn[t] + v, 0.f));
        g_minval[t] = val;
    }
    sv[t] = val; si[t] = t; skey[t] = key;
    __syncthreads();
    for (int s = 512; s > 0; s >>= 1) {
        if (t < s && t + s < 768) {
            if (sv[t + s] > sv[t] || (sv[t + s] == sv[t] && si[t + s] < si[t])) {
                sv[t] = sv[t + s]; si[t] = si[t + s]; skey[t] = skey[t + s];
            }
        }
        __syncthreads();
    }
    if (t == 0) {
        g_sidx = si[0];
        g_sstar = sv[0];
        g_mstar = (int)(skey[0] & 0xffffffffu);
    }
}

// ---------------- 4) fused d_star + per-block top5 (fp32 lib) ----------------
__global__ void dstar_top5(const float* __restrict__ lib) {
    __shared__ float4 q[96];
    __shared__ float smsn;
    __shared__ int sms;
    __shared__ ull wk[8][5];
    int t = threadIdx.x, warp = t >> 5, lane = t & 31;
    if (t == 0) sms = g_mstar;
    __syncthreads();
    if (t < 96) q[t] = ((const float4*)(lib + (size_t)sms * D))[t];
    if (t == 96) smsn = g_ln[sms];
    __syncthreads();
    ull top[5];
#pragma unroll
    for (int k = 0; k < 5; k++) top[k] = ~0ull;
    for (int it = 0; it < 100; it++) {
        long r = (long)blockIdx.x * 800 + it * 8 + warp;
        const float4* row = (const float4*)(lib + (size_t)r * D);
        float s = dot4f(row[lane], q[lane])
                + dot4f(row[lane + 32], q[lane + 32])
                + dot4f(row[lane + 64], q[lane + 64]);
        for (int o = 16; o > 0; o >>= 1) s += __shfl_down_sync(0xffffffffu, s, o);
        if (lane == 0) {
            float d2 = g_ln[r] + smsn - 2.f * s;
            ull key = ((ull)f2ord(d2) << 32) | (unsigned)r;
            if (key < top[4]) {
                top[4] = key;
#pragma unroll
                for (int k = 4; k > 0; k--)
                    if (top[k] < top[k - 1]) { ull tv = top[k]; top[k] = top[k - 1]; top[k - 1] = tv; }
            }
        }
    }
    if (lane == 0)
#pragma unroll
        for (int k = 0; k < 5; k++) wk[warp][k] = top[k];
    __syncthreads();
    if (t == 0) {
        ull last = 0;
        for (int sel = 0; sel < 5; sel++) {
            ull best = ~0ull;
            for (int i = 0; i < 40; i++) {
                ull k = wk[i / 5][i % 5];
                if (k > last && k < best) best = k;
            }
            g_part[blockIdx.x * 5 + sel] = best;
            last = best;
        }
    }
}

// ---------------- 5) merge top5 + scalar s (one kernel) ----------------
__global__ void finalize_kernel(const float* __restrict__ lib, float* __restrict__ out) {
    __shared__ ull keys[T5B * 5];
    __shared__ ull red[256];
    __shared__ int tgt[6];
    __shared__ float dd[6];
    int t = threadIdx.x;  // 256
    for (int i = t; i < T5B * 5; i += 256) keys[i] = g_part[i];
    __syncthreads();
    ull last = 0;
    for (int sel = 0; sel < 5; sel++) {
        ull best = ~0ull;
        for (int i = t; i < T5B * 5; i += 256) {
            ull k = keys[i];
            if (k > last && k < best) best = k;
        }
        red[t] = best;
        __syncthreads();
        for (int s = 128; s > 0; s >>= 1) {
            if (t < s) red[t] = min(red[t], red[t + s]);
            __syncthreads();
        }
        if (t == 0) tgt[sel] = (int)(red[0] & 0xffffffffu);
        last = red[0];
        __syncthreads();
    }
    if (t == 0) tgt[5] = g_mstar;
    __syncthreads();
    int warp = t >> 5, lane = t & 31;
    if (warp < 6) {
        long rm = tgt[warp];
        const float* p = g_patchN + (size_t)g_sidx * D;
        const float* q = lib + (size_t)rm * D;
        float s = 0.f;
        for (int c = lane; c < D; c += 32) {
            float d = p[c] - q[c];
            s += d * d;
        }
        for (int o = 16; o > 0; o >>= 1) s += __shfl_down_sync(0xffffffffu, s, o);
        if (lane == 0) dd[warp] = sqrtf(s);
    }
    __syncthreads();
    if (t == 0) {
        float den = 0.f;
        for (int k = 0; k < 5; k++) den += expf(dd[k]);
        float num = expf(dd[5]);
        out[0] = (1.f - num / den) * g_sstar;
    }
}

// ---------------- 6) fused resize + gaussian blur (one kernel) ----------------
__device__ __forceinline__ int reflect_idx(int i) {
    if (i < 0) return -i;
    if (i > IMG - 1) return 2 * (IMG - 1) - i;
    return i;
}

__global__ void smap_kernel(float* __restrict__ out) {
    // grid 224 (one output row per block), block 224
    __shared__ float mv[N_PATCH];
    __shared__ float trow[IMG];
    __shared__ float kw[KS];
    __shared__ int ry0[KS], ry1[KS];
    __shared__ float rwy[KS];
    int t = threadIdx.x, y = blockIdx.x;
    const float scale = 26.f / 224.f;
    for (int i = t; i < N_PATCH; i += IMG) mv[i] = g_minval[i];
    if (t < KS) {
        float xx = (float)(t - RAD);
        kw[t] = expf(-0.5f * (xx / 4.f) * (xx / 4.f));
        int ry = reflect_idx(y + t - RAD);
        float fy = (ry + 0.5f) * scale - 0.5f;
        float fy0 = floorf(fy);
        int y0 = (int)fy0;
        rwy[t] = fy - fy0;
        ry0[t] = min(max(y0, 0), 25) * 26;
        ry1[t] = min(max(y0 + 1, 0), 25) * 26;
    }
    __syncthreads();
    float wsum = 0.f;
#pragma unroll
    for (int d = 0; d < KS; d++) wsum += kw[d];

    int x = t;
    float fx = (x + 0.5f) * scale - 0.5f;
    float fx0 = floorf(fx);
    int x0 = min(max((int)fx0, 0), 25), x1 = min(max((int)fx0 + 1, 0), 25);
    float wx = fx - fx0;
    float acc = 0.f;
#pragma unroll
    for (int d = 0; d < KS; d++) {
        float v00 = mv[ry0[d] + x0], v01 = mv[ry0[d] + x1];
        float v10 = mv[ry1[d] + x0], v11 = mv[ry1[d] + x1];
        float wy = rwy[d];
        float r = (1.f - wy) * ((1.f - wx) * v00 + wx * v01)
                + wy * ((1.f - wx) * v10 + wx * v11);
        acc += kw[d] * r;
    }
    trow[x] = acc;
    __syncthreads();
    float acc2 = 0.f;
#pragma unroll
    for (int d = 0; d < KS; d++)
        acc2 += kw[d] * trow[reflect_idx(x + d - RAD)];
    out[1 + y * IMG + x] = acc2 / (wsum * wsum);
}

// ---------------- launch ----------------
extern "C" void kernel_launch(void* const* d_in, const int* in_sizes, int n_in,
                              void* d_out, int out_size) {
    const float* patch = (const float*)d_in[0];
    const float* lib   = (const float*)d_in[1];
    if (n_in >= 2 && in_sizes[0] > in_sizes[1]) {
        const float* tmp = patch; patch = lib; lib = tmp;
    }
    float* out = (float*)d_out;

    cudaFuncSetAttribute(gemm_bf16, cudaFuncAttributeMaxDynamicSharedMemorySize, SMEM_DYN);

    prep_kernel<<<NPAD, 128>>>(patch);
    gemm_bf16<<<dim3(NPT, NTILES), 256, SMEM_DYN>>>(lib);
    argmax_kernel<<<1, 768>>>();
    dstar_top5<<<T5B, 256>>>(lib);
    finalize_kernel<<<1, 256>>>(lib, out);
    smap_kernel<<<IMG, IMG>>>(out);
}

// round 11
// speedup vs baseline: 1.0092x; 1.0092x over previous
#include <cuda_runtime.h>
#include <cuda_bf16.h>
#include <math.h>
#include <stdint.h>

#define N_PATCH 676
#define NPAD    768
#define NPT     6          // patch tiles of 128
#define D       384
#define M       200000
#define NTILES  1563       // lib tiles of 128
#define NKB     6          // k-blocks of 64
#define IMG     224
#define KS      33
#define RAD     16
#define T5B     250        // dstar_top5 blocks

typedef unsigned long long ull;

__device__ __align__(16) __nv_bfloat16 g_patchh[NPAD * D];
__device__ float g_patchN[NPAD * D];
__device__ float g_pn[NPAD];
__device__ float g_ln[M];
__device__ ull   g_mink[NPAD];      // global per-patch-col min key (atomicMin)
__device__ float g_minval[N_PATCH];
__device__ int   g_sidx;
__device__ int   g_mstar;
__device__ float g_sstar;
__device__ ull   g_part[T5B * 5];

__device__ __forceinline__ uint32_t smem_u32(const void* p) {
    uint32_t a;
    asm("{ .reg .u64 t; cvta.to.shared.u64 t, %1; cvt.u32.u64 %0, t; }" : "=r"(a) : "l"(p));
    return a;
}
#define SW128(x) ((x) ^ (((x) >> 3) & 0x70))

#define CP16(dst, src) asm volatile("cp.async.cg.shared.global [%0], [%1], 16;" :: "r"(dst), "l"(src) : "memory")
#define CP_COMMIT()    asm volatile("cp.async.commit_group;" ::: "memory")
#define CP_WAIT1()     asm volatile("cp.async.wait_group 1;" ::: "memory")
#define CP_WAIT0()     asm volatile("cp.async.wait_group 0;" ::: "memory")

#define STS128(addr, v) \
    asm volatile("st.shared.v4.b32 [%0], {%1,%2,%3,%4};" \
        :: "r"(addr), "r"((v).x), "r"((v).y), "r"((v).z), "r"((v).w) : "memory")

#define LDSM4(r0, r1, r2, r3, addr) \
    asm volatile("ldmatrix.sync.aligned.m8n8.x4.shared.b16 {%0,%1,%2,%3}, [%4];" \
        : "=r"(r0), "=r"(r1), "=r"(r2), "=r"(r3) : "r"(addr))

#define MMA16816(c, a, b0, b1) \
    asm volatile("mma.sync.aligned.m16n8k16.row.col.f32.bf16.bf16.f32 " \
        "{%0,%1,%2,%3}, {%4,%5,%6,%7}, {%8,%9}, {%0,%1,%2,%3};" \
        : "+f"((c)[0]), "+f"((c)[1]), "+f"((c)[2]), "+f"((c)[3]) \
        : "r"((a)[0]), "r"((a)[1]), "r"((a)[2]), "r"((a)[3]), "r"(b0), "r"(b1))

__device__ __forceinline__ unsigned f2ord(float v) {
    unsigned u = __float_as_uint(v);
    return (u & 0x80000000u) ? ~u : (u | 0x80000000u);
}
__device__ __forceinline__ float ord2f(unsigned o) {
    unsigned u = (o & 0x80000000u) ? (o & 0x7fffffffu) : ~o;
    return __uint_as_float(u);
}

__device__ __forceinline__ float dot4f(float4 a, float4 b) {
    return a.x * b.x + a.y * b.y + a.z * b.z + a.w * b.w;
}

// ---------------- 1) normalize patch -> fp32 + bf16, pn; init g_mink ----------------
__global__ void prep_kernel(const float* __restrict__ patch) {
    int n = blockIdx.x, t = threadIdx.x;   // 128 threads
    __shared__ float red[4];
    __shared__ float bcast;
    if (t == 0) g_mink[n] = ~0ull;
    if (n >= N_PATCH) {
        for (int c = t; c < D; c += 128) {
            g_patchN[(size_t)n * D + c] = 0.f;
            g_patchh[(size_t)n * D + c] = __float2bfloat16(0.f);
        }
        if (t == 0) g_pn[n] = 0.f;
        return;
    }
    float x0 = patch[(size_t)n * D + t];
    float x1 = patch[(size_t)n * D + t + 128];
    float x2 = patch[(size_t)n * D + t + 256];
    float s = x0 * x0 + x1 * x1 + x2 * x2;
    for (int o = 16; o > 0; o >>= 1) s += __shfl_down_sync(0xffffffffu, s, o);
    if ((t & 31) == 0) red[t >> 5] = s;
    __syncthreads();
    if (t == 0) bcast = red[0] + red[1] + red[2] + red[3];
    __syncthreads();
    float inv = 1.f / fmaxf(sqrtf(bcast), 1e-12f);
    float y0 = x0 * inv, y1 = x1 * inv, y2 = x2 * inv;
    g_patchN[(size_t)n * D + t]       = y0;
    g_patchN[(size_t)n * D + t + 128] = y1;
    g_patchN[(size_t)n * D + t + 256] = y2;
    g_patchh[(size_t)n * D + t]       = __float2bfloat16(y0);
    g_patchh[(size_t)n * D + t + 128] = __float2bfloat16(y1);
    g_patchh[(size_t)n * D + t + 256] = __float2bfloat16(y2);
    float p = y0 * y0 + y1 * y1 + y2 * y2;
    for (int o = 16; o > 0; o >>= 1) p += __shfl_down_sync(0xffffffffu, p, o);
    if ((t & 31) == 0) red[t >> 5] = p;
    __syncthreads();
    if (t == 0) g_pn[n] = red[0] + red[1] + red[2] + red[3];
}

// ---------------- 2) bf16 HMMA GEMM, fp32 A converted in-flight, ln fused ----------------
// A stages (bf16) @ 0/16384, B stages (bf16) @ 32768/49152. 64KB dyn smem.
#define SMEM_DYN 65536

__global__ void __launch_bounds__(256, 2) gemm_bf16(const float* __restrict__ lib) {
    extern __shared__ char dyn[];
    __shared__ float ln_s[128];
    __shared__ ull scmb[2][128];

    int t = threadIdx.x;
    int pt = blockIdx.x;       // patch tile (fast -> lib tile L2 reuse)
    int tile = blockIdx.y;     // lib tile
    int lane = t & 31, warp = t >> 5;
    int wm = warp >> 2, wn = warp & 3;

    uint32_t sbase = smem_u32(dyn);
    const float* gA = lib + (size_t)tile * 128 * D;           // fp32 lib tile
    const char* gB = (const char*)g_patchh + (size_t)pt * 128 * 768;

    int arow = t >> 3;         // local row base (0..31), rows arow+32i
    int aseg = t & 7;          // 8-float segment within the 64-col k-block
    float acc0 = 0.f, acc1 = 0.f, acc2 = 0.f, acc3 = 0.f;

    // A loader: fp32 LDG -> bf16 cvt -> STS (row mapping identical to cp.async version)
#define LOADA(kb_, sb_) do { \
        _Pragma("unroll") \
        for (int i_ = 0; i_ < 4; i_++) { \
            int row_ = arow + 32 * i_; \
            float4 v0 = make_float4(0.f, 0.f, 0.f, 0.f); \
            float4 v1 = v0; \
            if (tile * 128 + row_ < M) { \
                const float4* p_ = (const float4*)(gA + (size_t)row_ * D + (kb_) * 64) + aseg * 2; \
                v0 = p_[0]; v1 = p_[1]; \
            } \
            float ss_ = v0.x * v0.x + v0.y * v0.y + v0.z * v0.z + v0.w * v0.w \
                      + v1.x * v1.x + v1.y * v1.y + v1.z * v1.z + v1.w * v1.w; \
            if (i_ == 0) acc0 += ss_; else if (i_ == 1) acc1 += ss_; \
            else if (i_ == 2) acc2 += ss_; else acc3 += ss_; \
            __nv_bfloat162 p0_ = __float22bfloat162_rn(make_float2(v0.x, v0.y)); \
            __nv_bfloat162 p1_ = __float22bfloat162_rn(make_float2(v0.z, v0.w)); \
            __nv_bfloat162 p2_ = __float22bfloat162_rn(make_float2(v1.x, v1.y)); \
            __nv_bfloat162 p3_ = __float22bfloat162_rn(make_float2(v1.z, v1.w)); \
            uint4 o_; \
            o_.x = *reinterpret_cast<unsigned*>(&p0_); \
            o_.y = *reinterpret_cast<unsigned*>(&p1_); \
            o_.z = *reinterpret_cast<unsigned*>(&p2_); \
            o_.w = *reinterpret_cast<unsigned*>(&p3_); \
            STS128((sb_) + SW128((uint32_t)(row_ * 128 + aseg * 16)), o_); \
        } \
    } while (0)

#define LOADB(kb_, sb_) do { \
        _Pragma("unroll") \
        for (int i_ = 0; i_ < 4; i_++) { \
            int id_ = i_ * 256 + t; int row_ = id_ >> 3, seg_ = id_ & 7; \
            uint32_t off_ = SW128((uint32_t)(row_ * 128 + seg_ * 16)); \
            CP16((sb_) + off_, gB + (size_t)(kb_) * 128 + (size_t)row_ * 768 + seg_ * 16); \
        } \
        CP_COMMIT(); \
    } while (0)

    // preload k-block 0
    LOADA(0, sbase);
    LOADB(0, sbase + 32768);

    float c[4][4][4];
#pragma unroll
    for (int mi = 0; mi < 4; mi++)
#pragma unroll
        for (int ni = 0; ni < 4; ni++)
#pragma unroll
            for (int k = 0; k < 4; k++) c[mi][ni][k] = 0.f;

    for (int kb = 0; kb < NKB; kb++) {
        int buf = kb & 1;
        if (kb < NKB - 1) {
            int nb = buf ^ 1;
            LOADA(kb + 1, sbase + nb * 16384);
            LOADB(kb + 1, sbase + 32768 + nb * 16384);
            CP_WAIT1();
        } else {
            CP_WAIT0();
        }
        __syncthreads();
        uint32_t sA = sbase + buf * 16384;
        uint32_t sB = sbase + 32768 + buf * 16384;
#pragma unroll
        for (int ks = 0; ks < 4; ks++) {
            uint32_t a[4][4];
#pragma unroll
            for (int mi = 0; mi < 4; mi++) {
                uint32_t byte = (uint32_t)((wm * 64 + mi * 16 + (lane & 15)) * 128
                                           + ks * 32 + (lane >> 4) * 16);
                LDSM4(a[mi][0], a[mi][1], a[mi][2], a[mi][3], sA + SW128(byte));
            }
            uint32_t b[4][2];
#pragma unroll
            for (int nh = 0; nh < 2; nh++) {
                uint32_t byte = (uint32_t)((wn * 32 + nh * 16 + (lane & 15)) * 128
                                           + ks * 32 + (lane >> 4) * 16);
                uint32_t r0, r1, r2, r3;
                LDSM4(r0, r1, r2, r3, sB + SW128(byte));
                b[nh * 2][0] = r0; b[nh * 2 + 1][0] = r1;
                b[nh * 2][1] = r2; b[nh * 2 + 1][1] = r3;
            }
#pragma unroll
            for (int mi = 0; mi < 4; mi++)
#pragma unroll
                for (int ni = 0; ni < 4; ni++)
                    MMA16816(c[mi][ni], a[mi], b[ni][0], b[ni][1]);
        }
        __syncthreads();
    }

    // ln: reduce per-row sumsq over the 8 seg-threads (lanes grouped by 8)
    {
        float av[4] = {acc0, acc1, acc2, acc3};
#pragma unroll
        for (int i = 0; i < 4; i++) {
            float s = av[i];
            s += __shfl_xor_sync(0xffffffffu, s, 1);
            s += __shfl_xor_sync(0xffffffffu, s, 2);
            s += __shfl_xor_sync(0xffffffffu, s, 4);
            int row = arow + 32 * i;
            int grow = tile * 128 + row;
            float lnv = (grow < M) ? s : 1e30f;
            if (aseg == 0) {
                ln_s[row] = lnv;
                if (pt == 0 && grow < M) g_ln[grow] = lnv;
            }
        }
    }
    __syncthreads();

    // epilogue: key = (f2ord(ln - 2 dot) << 32) | lib_row ; min over 128 rows per col
    unsigned rbase = (unsigned)tile * 128u + (unsigned)(wm * 64) + (unsigned)(lane >> 2);
#pragma unroll
    for (int ni = 0; ni < 4; ni++) {
        ull k0 = ~0ull, k1 = ~0ull;
#pragma unroll
        for (int mi = 0; mi < 4; mi++) {
            int rloc = wm * 64 + mi * 16 + (lane >> 2);
            float l0 = ln_s[rloc], l1 = ln_s[rloc + 8];
            unsigned r0 = rbase + mi * 16, r1 = r0 + 8;
            float v; ull k;
            v = fmaf(-2.f, c[mi][ni][0], l0); k = ((ull)f2ord(v) << 32) | r0; k0 = min(k0, k);
            v = fmaf(-2.f, c[mi][ni][2], l1); k = ((ull)f2ord(v) << 32) | r1; k0 = min(k0, k);
            v = fmaf(-2.f, c[mi][ni][1], l0); k = ((ull)f2ord(v) << 32) | r0; k1 = min(k1, k);
            v = fmaf(-2.f, c[mi][ni][3], l1); k = ((ull)f2ord(v) << 32) | r1; k1 = min(k1, k);
        }
#pragma unroll
        for (int off = 4; off < 32; off <<= 1) {
            k0 = min(k0, __shfl_xor_sync(0xffffffffu, k0, off));
            k1 = min(k1, __shfl_xor_sync(0xffffffffu, k1, off));
        }
        if (lane < 4) {
            scmb[wm][wn * 32 + ni * 8 + lane * 2 + 0] = k0;
            scmb[wm][wn * 32 + ni * 8 + lane * 2 + 1] = k1;
        }
    }
    __syncthreads();
    if (t < 128)
        atomicMin(&g_mink[pt * 128 + t], min(scmb[0][t], scmb[1][t]));
}

// ---------------- 3) finalize minval + argmax over patch rows ----------------
__global__ void argmax_kernel() {
    int t = threadIdx.x;  // 768
    __shared__ float sv[768];
    __shared__ int si[768];
    __shared__ ull skey[768];
    float val = -3.4e38f;
    ull key = ~0ull;
    if (t < N_PATCH) {
        key = g_mink[t];
        float v = ord2f((unsigned)(key >> 32));
        val = sqrtf(fmaxf(g_pn[t] + v, 0.f));
        g_minval[t] = val;
    }
    sv[t] = val; si[t] = t; skey[t] = key;
    __syncthreads();
    for (int s = 512; s > 0; s >>= 1) {
        if (t < s && t + s < 768) {
            if (sv[t + s] > sv[t] || (sv[t + s] == sv[t] && si[t + s] < si[t])) {
                sv[t] = sv[t + s]; si[t] = si[t + s]; skey[t] = skey[t + s];
            }
        }
        __syncthreads();
    }
    if (t == 0) {
        g_sidx = si[0];
        g_sstar = sv[0];
        g_mstar = (int)(skey[0] & 0xffffffffu);
    }
}

// ---------------- 4) fused d_star + per-block top5 (fp32 lib) ----------------
__global__ void dstar_top5(const float* __restrict__ lib) {
    __shared__ float4 q[96];
    __shared__ float smsn;
    __shared__ int sms;
    __shared__ ull wk[8][5];
    int t = threadIdx.x, warp = t >> 5, lane = t & 31;
    if (t == 0) sms = g_mstar;
    __syncthreads();
    if (t < 96) q[t] = ((const float4*)(lib + (size_t)sms * D))[t];
    if (t == 96) smsn = g_ln[sms];
    __syncthreads();
    ull top[5];
#pragma unroll
    for (int k = 0; k < 5; k++) top[k] = ~0ull;
    for (int it = 0; it < 100; it++) {
        long r = (long)blockIdx.x * 800 + it * 8 + warp;
        const float4* row = (const float4*)(lib + (size_t)r * D);
        float s = dot4f(row[lane], q[lane])
                + dot4f(row[lane + 32], q[lane + 32])
                + dot4f(row[lane + 64], q[lane + 64]);
        for (int o = 16; o > 0; o >>= 1) s += __shfl_down_sync(0xffffffffu, s, o);
        if (lane == 0) {
            float d2 = g_ln[r] + smsn - 2.f * s;
            ull key = ((ull)f2ord(d2) << 32) | (unsigned)r;
            if (key < top[4]) {
                top[4] = key;
#pragma unroll
                for (int k = 4; k > 0; k--)
                    if (top[k] < top[k - 1]) { ull tv = top[k]; top[k] = top[k - 1]; top[k - 1] = tv; }
            }
        }
    }
    if (lane == 0)
#pragma unroll
        for (int k = 0; k < 5; k++) wk[warp][k] = top[k];
    __syncthreads();
    if (t == 0) {
        ull last = 0;
        for (int sel = 0; sel < 5; sel++) {
            ull best = ~0ull;
            for (int i = 0; i < 40; i++) {
                ull k = wk[i / 5][i % 5];
                if (k > last && k < best) best = k;
            }
            g_part[blockIdx.x * 5 + sel] = best;
            last = best;
        }
    }
}

// ---------------- 5) merge top5 + scalar s (one kernel) ----------------
__global__ void finalize_kernel(const float* __restrict__ lib, float* __restrict__ out) {
    __shared__ ull keys[T5B * 5];
    __shared__ ull red[256];
    __shared__ int tgt[6];
    __shared__ float dd[6];
    int t = threadIdx.x;  // 256
    for (int i = t; i < T5B * 5; i += 256) keys[i] = g_part[i];
    __syncthreads();
    ull last = 0;
    for (int sel = 0; sel < 5; sel++) {
        ull best = ~0ull;
        for (int i = t; i < T5B * 5; i += 256) {
            ull k = keys[i];
            if (k > last && k < best) best = k;
        }
        red[t] = best;
        __syncthreads();
        for (int s = 128; s > 0; s >>= 1) {
            if (t < s) red[t] = min(red[t], red[t + s]);
            __syncthreads();
        }
        if (t == 0) tgt[sel] = (int)(red[0] & 0xffffffffu);
        last = red[0];
        __syncthreads();
    }
    if (t == 0) tgt[5] = g_mstar;
    __syncthreads();
    int warp = t >> 5, lane = t & 31;
    if (warp < 6) {
        long rm = tgt[warp];
        const float* p = g_patchN + (size_t)g_sidx * D;
        const float* q = lib + (size_t)rm * D;
        float s = 0.f;
        for (int c = lane; c < D; c += 32) {
            float d = p[c] - q[c];
            s += d * d;
        }
        for (int o = 16; o > 0; o >>= 1) s += __shfl_down_sync(0xffffffffu, s, o);
        if (lane == 0) dd[warp] = sqrtf(s);
    }
    __syncthreads();
    if (t == 0) {
        float den = 0.f;
        for (int k = 0; k < 5; k++) den += expf(dd[k]);
        float num = expf(dd[5]);
        out[0] = (1.f - num / den) * g_sstar;
    }
}

// ---------------- 6) fused resize + gaussian blur (one kernel) ----------------
__device__ __forceinline__ int reflect_idx(int i) {
    if (i < 0) return -i;
    if (i > IMG - 1) return 2 * (IMG - 1) - i;
    return i;
}

__global__ void smap_kernel(float* __restrict__ out) {
    // grid 224 (one output row per block), block 224
    __shared__ float mv[N_PATCH];
    __shared__ float trow[IMG];
    __shared__ float kw[KS];
    __shared__ int ry0[KS], ry1[KS];
    __shared__ float rwy[KS];
    int t = threadIdx.x, y = blockIdx.x;
    const float scale = 26.f / 224.f;
    for (int i = t; i < N_PATCH; i += IMG) mv[i] = g_minval[i];
    if (t < KS) {
        float xx = (float)(t - RAD);
        kw[t] = expf(-0.5f * (xx / 4.f) * (xx / 4.f));
        int ry = reflect_idx(y + t - RAD);
        float fy = (ry + 0.5f) * scale - 0.5f;
        float fy0 = floorf(fy);
        int y0 = (int)fy0;
        rwy[t] = fy - fy0;
        ry0[t] = min(max(y0, 0), 25) * 26;
        ry1[t] = min(max(y0 + 1, 0), 25) * 26;
    }
    __syncthreads();
    float wsum = 0.f;
#pragma unroll
    for (int d = 0; d < KS; d++) wsum += kw[d];

    int x = t;
    float fx = (x + 0.5f) * scale - 0.5f;
    float fx0 = floorf(fx);
    int x0 = min(max((int)fx0, 0), 25), x1 = min(max((int)fx0 + 1, 0), 25);
    float wx = fx - fx0;
    float acc = 0.f;
#pragma unroll
    for (int d = 0; d < KS; d++) {
        float v00 = mv[ry0[d] + x0], v01 = mv[ry0[d] + x1];
        float v10 = mv[ry1[d] + x0], v11 = mv[ry1[d] + x1];
        float wy = rwy[d];
        float r = (1.f - wy) * ((1.f - wx) * v00 + wx * v01)
                + wy * ((1.f - wx) * v10 + wx * v11);
        acc += kw[d] * r;
    }
    trow[x] = acc;
    __syncthreads();
    float acc2 = 0.f;
#pragma unroll
    for (int d = 0; d < KS; d++)
        acc2 += kw[d] * trow[reflect_idx(x + d - RAD)];
    out[1 + y * IMG + x] = acc2 / (wsum * wsum);
}

// ---------------- launch ----------------
extern "C" void kernel_launch(void* const* d_in, const int* in_sizes, int n_in,
                              void* d_out, int out_size) {
    const float* patch = (const float*)d_in[0];
    const float* lib   = (const float*)d_in[1];
    if (n_in >= 2 && in_sizes[0] > in_sizes[1]) {
        const float* tmp = patch; patch = lib; lib = tmp;
    }
    float* out = (float*)d_out;

    cudaFuncSetAttribute(gemm_bf16, cudaFuncAttributeMaxDynamicSharedMemorySize, SMEM_DYN);

    prep_kernel<<<NPAD, 128>>>(patch);
    gemm_bf16<<<dim3(NPT, NTILES), 256, SMEM_DYN>>>(lib);
    argmax_kernel<<<1, 768>>>();
    dstar_top5<<<T5B, 256>>>(lib);
    finalize_kernel<<<1, 256>>>(lib, out);
    smap_kernel<<<IMG, IMG>>>(out);
}

// round 16
// speedup vs baseline: 1.1798x; 1.1691x over previous
#include <cuda_runtime.h>
#include <cuda_bf16.h>
#include <math.h>
#include <stdint.h>

#define N_PATCH 676
#define NPAD    768
#define NPT     6          // patch tiles of 128
#define D       384
#define M       200000
#define NTILES  1563       // lib tiles of 128
#define MPAD    (NTILES * 128)
#define NKB     6          // k-blocks of 64
#define IMG     224
#define KS      33
#define RAD     16
#define T5B     250        // dstar_top5 blocks

typedef unsigned long long ull;

__device__ __align__(128) __nv_bfloat16 g_libh[(size_t)MPAD * D];
__device__ __align__(16)  __nv_bfloat16 g_patchh[NPAD * D];
__device__ float g_patchN[NPAD * D];
__device__ float g_pn[NPAD];
__device__ float g_ln[MPAD];
__device__ ull   g_mink[NPAD];      // global per-patch-col min key (atomicMin)
__device__ float g_minval[N_PATCH];
__device__ int   g_sidx;
__device__ int   g_mstar;
__device__ float g_sstar;
__device__ ull   g_part[T5B * 5];

__device__ __forceinline__ uint32_t smem_u32(const void* p) {
    uint32_t a;
    asm("{ .reg .u64 t; cvta.to.shared.u64 t, %1; cvt.u32.u64 %0, t; }" : "=r"(a) : "l"(p));
    return a;
}
#define SW128(x) ((x) ^ (((x) >> 3) & 0x70))

#define CP16(dst, src) asm volatile("cp.async.cg.shared.global [%0], [%1], 16;" :: "r"(dst), "l"(src) : "memory")
#define CP_COMMIT()    asm volatile("cp.async.commit_group;" ::: "memory")
#define CP_WAIT1()     asm volatile("cp.async.wait_group 1;" ::: "memory")
#define CP_WAIT0()     asm volatile("cp.async.wait_group 0;" ::: "memory")

#define LDSM4(r0, r1, r2, r3, addr) \
    asm volatile("ldmatrix.sync.aligned.m8n8.x4.shared.b16 {%0,%1,%2,%3}, [%4];" \
        : "=r"(r0), "=r"(r1), "=r"(r2), "=r"(r3) : "r"(addr))

#define MMA16816(c, a, b0, b1) \
    asm volatile("mma.sync.aligned.m16n8k16.row.col.f32.bf16.bf16.f32 " \
        "{%0,%1,%2,%3}, {%4,%5,%6,%7}, {%8,%9}, {%0,%1,%2,%3};" \
        : "+f"((c)[0]), "+f"((c)[1]), "+f"((c)[2]), "+f"((c)[3]) \
        : "r"((a)[0]), "r"((a)[1]), "r"((a)[2]), "r"((a)[3]), "r"(b0), "r"(b1))

__device__ __forceinline__ unsigned f2ord(float v) {
    unsigned u = __float_as_uint(v);
    return (u & 0x80000000u) ? ~u : (u | 0x80000000u);
}
__device__ __forceinline__ float ord2f(unsigned o) {
    unsigned u = (o & 0x80000000u) ? (o & 0x7fffffffu) : ~o;
    return __uint_as_float(u);
}

__device__ __forceinline__ float dot8(uint4 a, uint4 b) {
    const unsigned* pa = (const unsigned*)&a;
    const unsigned* pb = (const unsigned*)&b;
    float s = 0.f;
#pragma unroll
    for (int i = 0; i < 4; i++) {
        float2 fa = __bfloat1622float2(*(const __nv_bfloat162*)&pa[i]);
        float2 fb = __bfloat1622float2(*(const __nv_bfloat162*)&pb[i]);
        s += fa.x * fb.x + fa.y * fb.y;
    }
    return s;
}

// ---------------- 1) normalize patch -> fp32 + bf16, pn; init g_mink ----------------
__global__ void prep_kernel(const float* __restrict__ patch) {
    int n = blockIdx.x, t = threadIdx.x;   // 128 threads
    __shared__ float red[4];
    __shared__ float bcast;
    if (t == 0) g_mink[n] = ~0ull;
    if (n >= N_PATCH) {
        for (int c = t; c < D; c += 128) {
            g_patchN[(size_t)n * D + c] = 0.f;
            g_patchh[(size_t)n * D + c] = __float2bfloat16(0.f);
        }
        if (t == 0) g_pn[n] = 0.f;
        return;
    }
    float x0 = patch[(size_t)n * D + t];
    float x1 = patch[(size_t)n * D + t + 128];
    float x2 = patch[(size_t)n * D + t + 256];
    float s = x0 * x0 + x1 * x1 + x2 * x2;
    for (int o = 16; o > 0; o >>= 1) s += __shfl_down_sync(0xffffffffu, s, o);
    if ((t & 31) == 0) red[t >> 5] = s;
    __syncthreads();
    if (t == 0) bcast = red[0] + red[1] + red[2] + red[3];
    __syncthreads();
    float inv = 1.f / fmaxf(sqrtf(bcast), 1e-12f);
    float y0 = x0 * inv, y1 = x1 * inv, y2 = x2 * inv;
    g_patchN[(size_t)n * D + t]       = y0;
    g_patchN[(size_t)n * D + t + 128] = y1;
    g_patchN[(size_t)n * D + t + 256] = y2;
    g_patchh[(size_t)n * D + t]       = __float2bfloat16(y0);
    g_patchh[(size_t)n * D + t + 128] = __float2bfloat16(y1);
    g_patchh[(size_t)n * D + t + 256] = __float2bfloat16(y2);
    float p = y0 * y0 + y1 * y1 + y2 * y2;
    for (int o = 16; o > 0; o >>= 1) p += __shfl_down_sync(0xffffffffu, p, o);
    if ((t & 31) == 0) red[t >> 5] = p;
    __syncthreads();
    if (t == 0) g_pn[n] = red[0] + red[1] + red[2] + red[3];
}

// ---------------- 2) lib fp32 -> bf16 + row norms (R7 version) ----------------
__global__ void convert_kernel(const float* __restrict__ lib) {
    int t = threadIdx.x, warp = t >> 5, lane = t & 31;
    long r = (long)blockIdx.x * 8 + warp;
    if (r >= MPAD) return;
    uint2* dst = (uint2*)(g_libh + (size_t)r * D);
    if (r >= M) {
        uint2 z = make_uint2(0u, 0u);
        for (int c = lane; c < 96; c += 32) dst[c] = z;
        if (lane == 0) g_ln[r] = 1e30f;
        return;
    }
    const float4* row = (const float4*)(lib + (size_t)r * D);
    float s = 0.f;
#pragma unroll
    for (int j = 0; j < 3; j++) {
        float4 v = row[lane + 32 * j];
        s += v.x * v.x + v.y * v.y + v.z * v.z + v.w * v.w;
        __nv_bfloat162 p0 = __float22bfloat162_rn(make_float2(v.x, v.y));
        __nv_bfloat162 p1 = __float22bfloat162_rn(make_float2(v.z, v.w));
        uint2 o;
        o.x = *reinterpret_cast<unsigned*>(&p0);
        o.y = *reinterpret_cast<unsigned*>(&p1);
        dst[lane + 32 * j] = o;
    }
    for (int o = 16; o > 0; o >>= 1) s += __shfl_down_sync(0xffffffffu, s, o);
    if (lane == 0) g_ln[r] = s;
}

// ---------------- 3) bf16 HMMA GEMM, 2-stage pipeline (R7 loop, verbatim) ----------------
// As[2] @ 0/16384 (16KB each), Bs[2] @ 32768/49152. Total 64KB dyn smem.
#define SMEM_DYN 65536

__global__ void __launch_bounds__(256, 2) gemm_bf16() {
    extern __shared__ char dyn[];
    __shared__ float ln_s[128];
    __shared__ ull scmb[2][128];

    int t = threadIdx.x;
    int pt = blockIdx.x;       // patch tile (fast -> lib tile L2 reuse)
    int tile = blockIdx.y;     // lib tile
    int lane = t & 31, warp = t >> 5;
    int wm = warp >> 2, wn = warp & 3;

    uint32_t sbase = smem_u32(dyn);
    const char* gA = (const char*)g_libh + (size_t)tile * 128 * 768;
    const char* gB = (const char*)g_patchh + (size_t)pt * 128 * 768;

    if (t < 128) ln_s[t] = g_ln[(size_t)tile * 128 + t];

    // preload k-block 0
#pragma unroll
    for (int i = 0; i < 4; i++) {
        int id = i * 256 + t; int row = id >> 3, seg = id & 7;
        uint32_t off = SW128((uint32_t)(row * 128 + seg * 16));
        CP16(sbase + off, gA + (size_t)row * 768 + seg * 16);
        CP16(sbase + 32768 + off, gB + (size_t)row * 768 + seg * 16);
    }
    CP_COMMIT();

    float c[4][4][4];
#pragma unroll
    for (int mi = 0; mi < 4; mi++)
#pragma unroll
        for (int ni = 0; ni < 4; ni++)
#pragma unroll
            for (int k = 0; k < 4; k++) c[mi][ni][k] = 0.f;

    for (int kb = 0; kb < NKB; kb++) {
        int buf = kb & 1;
        if (kb < NKB - 1) {
            int nb = buf ^ 1;
            const char* ga = gA + (kb + 1) * 128;
            const char* gb = gB + (kb + 1) * 128;
#pragma unroll
            for (int i = 0; i < 4; i++) {
                int id = i * 256 + t; int row = id >> 3, seg = id & 7;
                uint32_t off = SW128((uint32_t)(row * 128 + seg * 16));
                CP16(sbase + nb * 16384 + off, ga + (size_t)row * 768 + seg * 16);
                CP16(sbase + 32768 + nb * 16384 + off, gb + (size_t)row * 768 + seg * 16);
            }
            CP_COMMIT();
            CP_WAIT1();
        } else {
            CP_WAIT0();
        }
        __syncthreads();
        uint32_t sA = sbase + buf * 16384;
        uint32_t sB = sbase + 32768 + buf * 16384;
#pragma unroll
        for (int ks = 0; ks < 4; ks++) {
            uint32_t a[4][4];
#pragma unroll
            for (int mi = 0; mi < 4; mi++) {
                uint32_t byte = (uint32_t)((wm * 64 + mi * 16 + (lane & 15)) * 128
                                           + ks * 32 + (lane >> 4) * 16);
                LDSM4(a[mi][0], a[mi][1], a[mi][2], a[mi][3], sA + SW128(byte));
            }
            uint32_t b[4][2];
#pragma unroll
            for (int nh = 0; nh < 2; nh++) {
                uint32_t byte = (uint32_t)((wn * 32 + nh * 16 + (lane & 15)) * 128
                                           + ks * 32 + (lane >> 4) * 16);
                uint32_t r0, r1, r2, r3;
                LDSM4(r0, r1, r2, r3, sB + SW128(byte));
                b[nh * 2][0] = r0; b[nh * 2 + 1][0] = r1;
                b[nh * 2][1] = r2; b[nh * 2 + 1][1] = r3;
            }
#pragma unroll
            for (int mi = 0; mi < 4; mi++)
#pragma unroll
                for (int ni = 0; ni < 4; ni++)
                    MMA16816(c[mi][ni], a[mi], b[ni][0], b[ni][1]);
        }
        __syncthreads();
    }

    // epilogue: key = (f2ord(ln - 2 dot) << 32) | lib_row ; min over 128 rows per col
    unsigned rbase = (unsigned)tile * 128u + (unsigned)(wm * 64) + (unsigned)(lane >> 2);
#pragma unroll
    for (int ni = 0; ni < 4; ni++) {
        ull k0 = ~0ull, k1 = ~0ull;
#pragma unroll
        for (int mi = 0; mi < 4; mi++) {
            int rloc = wm * 64 + mi * 16 + (lane >> 2);
            float l0 = ln_s[rloc], l1 = ln_s[rloc + 8];
            unsigned r0 = rbase + mi * 16, r1 = r0 + 8;
            float v; ull k;
            v = fmaf(-2.f, c[mi][ni][0], l0); k = ((ull)f2ord(v) << 32) | r0; k0 = min(k0, k);
            v = fmaf(-2.f, c[mi][ni][2], l1); k = ((ull)f2ord(v) << 32) | r1; k0 = min(k0, k);
            v = fmaf(-2.f, c[mi][ni][1], l0); k = ((ull)f2ord(v) << 32) | r0; k1 = min(k1, k);
            v = fmaf(-2.f, c[mi][ni][3], l1); k = ((ull)f2ord(v) << 32) | r1; k1 = min(k1, k);
        }
#pragma unroll
        for (int off = 4; off < 32; off <<= 1) {
            k0 = min(k0, __shfl_xor_sync(0xffffffffu, k0, off));
            k1 = min(k1, __shfl_xor_sync(0xffffffffu, k1, off));
        }
        if (lane < 4) {
            scmb[wm][wn * 32 + ni * 8 + lane * 2 + 0] = k0;
            scmb[wm][wn * 32 + ni * 8 + lane * 2 + 1] = k1;
        }
    }
    __syncthreads();
    if (t < 128)
        atomicMin(&g_mink[pt * 128 + t], min(scmb[0][t], scmb[1][t]));
}

// ---------------- 4) finalize minval + argmax over patch rows ----------------
__global__ void argmax_kernel() {
    int t = threadIdx.x;  // 768
    __shared__ float sv[768];
    __shared__ int si[768];
    __shared__ ull skey[768];
    float val = -3.4e38f;
    ull key = ~0ull;
    if (t < N_PATCH) {
        key = g_mink[t];
        float v = ord2f((unsigned)(key >> 32));
        val = sqrtf(fmaxf(g_pn[t] + v, 0.f));
        g_minval[t] = val;
    }
    sv[t] = val; si[t] = t; skey[t] = key;
    __syncthreads();
    for (int s = 512; s > 0; s >>= 1) {
        if (t < s && t + s < 768) {
            if (sv[t + s] > sv[t] || (sv[t + s] == sv[t] && si[t + s] < si[t])) {
                sv[t] = sv[t + s]; si[t] = si[t + s]; skey[t] = skey[t + s];
            }
        }
        __syncthreads();
    }
    if (t == 0) {
        g_sidx = si[0];
        g_sstar = sv[0];
        g_mstar = (int)(skey[0] & 0xffffffffu);
    }
}

// ---------------- 5) fused d_star + per-block top5 (bf16 lib) ----------------
__global__ void dstar_top5() {
    __shared__ uint4 q[48];
    __shared__ float smsn;
    __shared__ int sms;
    __shared__ ull wk[8][5];
    int t = threadIdx.x, warp = t >> 5, lane = t & 31;
    if (t == 0) sms = g_mstar;
    __syncthreads();
    if (t < 48) q[t] = ((const uint4*)(g_libh + (size_t)sms * D))[t];
    if (t == 63) smsn = g_ln[sms];
    __syncthreads();
    ull top[5];
#pragma unroll
    for (int k = 0; k < 5; k++) top[k] = ~0ull;
    for (int it = 0; it < 100; it++) {
        long r = (long)blockIdx.x * 800 + it * 8 + warp;
        const uint4* row = (const uint4*)(g_libh + (size_t)r * D);
        float s = dot8(row[lane], q[lane]);
        if (lane < 16) s += dot8(row[32 + lane], q[32 + lane]);
        for (int o = 16; o > 0; o >>= 1) s += __shfl_down_sync(0xffffffffu, s, o);
        if (lane == 0) {
            float d2 = g_ln[r] + smsn - 2.f * s;
            ull key = ((ull)f2ord(d2) << 32) | (unsigned)r;
            if (key < top[4]) {
                top[4] = key;
#pragma unroll
                for (int k = 4; k > 0; k--)
                    if (top[k] < top[k - 1]) { ull tv = top[k]; top[k] = top[k - 1]; top[k - 1] = tv; }
            }
        }
    }
    if (lane == 0)
#pragma unroll
        for (int k = 0; k < 5; k++) wk[warp][k] = top[k];
    __syncthreads();
    if (t == 0) {
        ull last = 0;
        for (int sel = 0; sel < 5; sel++) {
            ull best = ~0ull;
            for (int i = 0; i < 40; i++) {
                ull k = wk[i / 5][i % 5];
                if (k > last && k < best) best = k;
            }
            g_part[blockIdx.x * 5 + sel] = best;
            last = best;
        }
    }
}

// ---------------- 6) merge top5 + scalar s (one kernel) ----------------
__global__ void finalize_kernel(const float* __restrict__ lib, float* __restrict__ out) {
    __shared__ ull keys[T5B * 5];
    __shared__ ull red[256];
    __shared__ int tgt[6];
    __shared__ float dd[6];
    int t = threadIdx.x;  // 256
    for (int i = t; i < T5B * 5; i += 256) keys[i] = g_part[i];
    __syncthreads();
    ull last = 0;
    for (int sel = 0; sel < 5; sel++) {
        ull best = ~0ull;
        for (int i = t; i < T5B * 5; i += 256) {
            ull k = keys[i];
            if (k > last && k < best) best = k;
        }
        red[t] = best;
        __syncthreads();
        for (int s = 128; s > 0; s >>= 1) {
            if (t < s) red[t] = min(red[t], red[t + s]);
            __syncthreads();
        }
        if (t == 0) tgt[sel] = (int)(red[0] & 0xffffffffu);
        last = red[0];
        __syncthreads();
    }
    if (t == 0) tgt[5] = g_mstar;
    __syncthreads();
    int warp = t >> 5, lane = t & 31;
    if (warp < 6) {
        long rm = tgt[warp];
        const float* p = g_patchN + (size_t)g_sidx * D;
        const float* q = lib + (size_t)rm * D;
        float s = 0.f;
        for (int c = lane; c < D; c += 32) {
            float d = p[c] - q[c];
            s += d * d;
        }
        for (int o = 16; o > 0; o >>= 1) s += __shfl_down_sync(0xffffffffu, s, o);
        if (lane == 0) dd[warp] = sqrtf(s);
    }
    __syncthreads();
    if (t == 0) {
        float den = 0.f;
        for (int k = 0; k < 5; k++) den += expf(dd[k]);
        float num = expf(dd[5]);
        out[0] = (1.f - num / den) * g_sstar;
    }
}

// ---------------- 7) fused resize + gaussian blur (one kernel) ----------------
__device__ __forceinline__ int reflect_idx(int i) {
    if (i < 0) return -i;
    if (i > IMG - 1) return 2 * (IMG - 1) - i;
    return i;
}

__global__ void smap_kernel(float* __restrict__ out) {
    // grid 224 (one output row per block), block 224
    __shared__ float mv[N_PATCH];
    __shared__ float trow[IMG];
    __shared__ float kw[KS];
    __shared__ int ry0[KS], ry1[KS];
    __shared__ float rwy[KS];
    int t = threadIdx.x, y = blockIdx.x;
    const float scale = 26.f / 224.f;
    for (int i = t; i < N_PATCH; i += IMG) mv[i] = g_minval[i];
    if (t < KS) {
        float xx = (float)(t - RAD);
        kw[t] = expf(-0.5f * (xx / 4.f) * (xx / 4.f));
        int ry = reflect_idx(y + t - RAD);
        float fy = (ry + 0.5f) * scale - 0.5f;
        float fy0 = floorf(fy);
        int y0 = (int)fy0;
        rwy[t] = fy - fy0;
        ry0[t] = min(max(y0, 0), 25) * 26;
        ry1[t] = min(max(y0 + 1, 0), 25) * 26;
    }
    __syncthreads();
    float wsum = 0.f;
#pragma unroll
    for (int d = 0; d < KS; d++) wsum += kw[d];

    int x = t;
    float fx = (x + 0.5f) * scale - 0.5f;
    float fx0 = floorf(fx);
    int x0 = min(max((int)fx0, 0), 25), x1 = min(max((int)fx0 + 1, 0), 25);
    float wx = fx - fx0;
    float acc = 0.f;
#pragma unroll
    for (int d = 0; d < KS; d++) {
        float v00 = mv[ry0[d] + x0], v01 = mv[ry0[d] + x1];
        float v10 = mv[ry1[d] + x0], v11 = mv[ry1[d] + x1];
        float wy = rwy[d];
        float r = (1.f - wy) * ((1.f - wx) * v00 + wx * v01)
                + wy * ((1.f - wx) * v10 + wx * v11);
        acc += kw[d] * r;
    }
    trow[x] = acc;
    __syncthreads();
    float acc2 = 0.f;
#pragma unroll
    for (int d = 0; d < KS; d++)
        acc2 += kw[d] * trow[reflect_idx(x + d - RAD)];
    out[1 + y * IMG + x] = acc2 / (wsum * wsum);
}

// ---------------- launch ----------------
extern "C" void kernel_launch(void* const* d_in, const int* in_sizes, int n_in,
                              void* d_out, int out_size) {
    const float* patch = (const float*)d_in[0];
    const float* lib   = (const float*)d_in[1];
    if (n_in >= 2 && in_sizes[0] > in_sizes[1]) {
        const float* tmp = patch; patch = lib; lib = tmp;
    }
    float* out = (float*)d_out;

    cudaFuncSetAttribute(gemm_bf16, cudaFuncAttributeMaxDynamicSharedMemorySize, SMEM_DYN);

    prep_kernel<<<NPAD, 128>>>(patch);
    convert_kernel<<<MPAD / 8, 256>>>(lib);
    gemm_bf16<<<dim3(NPT, NTILES), 256, SMEM_DYN>>>();
    argmax_kernel<<<1, 768>>>();
    dstar_top5<<<T5B, 256>>>();
    finalize_kernel<<<1, 256>>>(lib, out);
    smap_kernel<<<IMG, IMG>>>(out);
}